// round 1
// baseline (speedup 1.0000x reference)
#include <cuda_runtime.h>
#include <math.h>

// ---------------- problem constants ----------------
#define BB 2
#define LL 2048
#define DD 256
#define SS 8
#define DEPTH 4
#define VOCAB 32000
#define EE (DD + SS)        // 264
#define ROWS (BB * LL)      // 4096

// ---------------- scratch (device globals; no cudaMalloc allowed) ----------------
__device__ float g_h[ROWS * DD];      // layer activations
__device__ float g_hn[ROWS * DD];     // layernorm output
__device__ float g_comb[ROWS * EE];   // combined / concat(embed_part, states)
__device__ float g_gate[ROWS * SS];   // gates

// ---------------- embedding gather ----------------
__global__ void embed_kernel(const int* __restrict__ x, const float* __restrict__ table) {
    int row = blockIdx.x;
    int d = threadIdx.x;
    g_h[row * DD + d] = table[(size_t)x[row] * DD + d];
}

// ---------------- generic SGEMM with bias: C[M,N] = A[M,K] @ B[K,N] + bias[N] ----------------
// A row stride == K, B row stride == N, C row stride == N.
// Requires: M % BM == 0, K % BK == 0, N % 4 == 0. N edge tiles handled by guards.
template<int BM, int BN, int BK, int TM, int TN>
__global__ void sgemm_bias_kernel(const float* __restrict__ A,
                                  const float* __restrict__ B,
                                  const float* __restrict__ bias,
                                  float* __restrict__ C,
                                  int M, int N, int K) {
    constexpr int THREADS = (BM / TM) * (BN / TN);
    __shared__ float As[BK][BM];
    __shared__ float Bs[BK][BN];

    const int tid = threadIdx.x;
    const int tcol = tid % (BN / TN);
    const int trow = tid / (BN / TN);
    const int row0 = blockIdx.y * BM;
    const int col0 = blockIdx.x * BN;

    constexpr int A_TPR = BK / 4;                 // threads per A row (float4 along K)
    const int aRow = tid / A_TPR;
    const int aCol = (tid % A_TPR) * 4;
    constexpr int A_RSTRIDE = THREADS / A_TPR;

    constexpr int B_TPR = BN / 4;                 // threads per B row (float4 along N)
    const int bRow = tid / B_TPR;
    const int bCol = (tid % B_TPR) * 4;
    constexpr int B_RSTRIDE = THREADS / B_TPR;

    float acc[TM][TN];
#pragma unroll
    for (int i = 0; i < TM; i++)
#pragma unroll
        for (int j = 0; j < TN; j++) acc[i][j] = 0.f;

    float regM[TM], regN[TN];

    for (int k0 = 0; k0 < K; k0 += BK) {
        // load A tile (BM x BK), store transposed
#pragma unroll
        for (int r = aRow; r < BM; r += A_RSTRIDE) {
            float4 v = *(const float4*)(&A[(size_t)(row0 + r) * K + k0 + aCol]);
            As[aCol + 0][r] = v.x;
            As[aCol + 1][r] = v.y;
            As[aCol + 2][r] = v.z;
            As[aCol + 3][r] = v.w;
        }
        // load B tile (BK x BN), guard N edge (N % 4 == 0 so whole float4 valid or not)
#pragma unroll
        for (int r = bRow; r < BK; r += B_RSTRIDE) {
            float4 v = make_float4(0.f, 0.f, 0.f, 0.f);
            if (col0 + bCol < N)
                v = *(const float4*)(&B[(size_t)(k0 + r) * N + col0 + bCol]);
            *(float4*)&Bs[r][bCol] = v;
        }
        __syncthreads();

#pragma unroll
        for (int k = 0; k < BK; k++) {
#pragma unroll
            for (int i = 0; i < TM; i++) regM[i] = As[k][trow * TM + i];
#pragma unroll
            for (int j = 0; j < TN; j++) regN[j] = Bs[k][tcol * TN + j];
#pragma unroll
            for (int i = 0; i < TM; i++)
#pragma unroll
                for (int j = 0; j < TN; j++) acc[i][j] += regM[i] * regN[j];
        }
        __syncthreads();
    }

#pragma unroll
    for (int i = 0; i < TM; i++) {
        int r = row0 + trow * TM + i;
#pragma unroll
        for (int j = 0; j < TN; j += 4) {
            int c = col0 + tcol * TN + j;
            if (c < N) {   // N % 4 == 0 -> whole float4 in-bounds
                float4 bv = *(const float4*)(&bias[c]);
                float4 o;
                o.x = acc[i][j + 0] + bv.x;
                o.y = acc[i][j + 1] + bv.y;
                o.z = acc[i][j + 2] + bv.z;
                o.w = acc[i][j + 3] + bv.w;
                *(float4*)(&C[(size_t)r * N + c]) = o;
            }
        }
    }
}

// ---------------- gate: sigmoid(combined @ Wg + bg), one warp per row ----------------
__global__ void gate_kernel(const float* __restrict__ Wg, const float* __restrict__ bg) {
    int warp = threadIdx.x >> 5;
    int lane = threadIdx.x & 31;
    int row = blockIdx.x * 8 + warp;

    float acc[SS];
#pragma unroll
    for (int s = 0; s < SS; s++) acc[s] = 0.f;

    for (int e = lane; e < EE; e += 32) {
        float a = g_comb[(size_t)row * EE + e];
        float4 w0 = *(const float4*)(Wg + (size_t)e * SS);
        float4 w1 = *(const float4*)(Wg + (size_t)e * SS + 4);
        acc[0] += a * w0.x; acc[1] += a * w0.y; acc[2] += a * w0.z; acc[3] += a * w0.w;
        acc[4] += a * w1.x; acc[5] += a * w1.y; acc[6] += a * w1.z; acc[7] += a * w1.w;
    }
#pragma unroll
    for (int s = 0; s < SS; s++)
#pragma unroll
        for (int off = 16; off > 0; off >>= 1)
            acc[s] += __shfl_down_sync(0xffffffffu, acc[s], off);

    if (lane == 0) {
#pragma unroll
        for (int s = 0; s < SS; s++) {
            float z = acc[s] + bg[s];
            g_gate[(size_t)row * SS + s] = 1.f / (1.f + expf(-z));
        }
    }
}

// ---------------- linear recurrence via affine-map prefix scan ----------------
// state_t = g_t * state_{t-1} + (1-g_t)*sin_t ; one block per (b,s) chain.
// Writes states back into g_comb[row*EE + DD + s] (in-place -> concat buffer for Wo GEMM).
__global__ void scan_kernel(float* __restrict__ finals, int layer) {
    __shared__ float sA[256];
    __shared__ float sB[256];
    const int b = blockIdx.x >> 3;   // / SS
    const int s = blockIdx.x & 7;    // % SS
    const int tid = threadIdx.x;
    constexpr int CH = LL / 256;     // 8 timesteps per thread

    const int t0 = tid * CH;
    float gl[CH], cl[CH];
    float A = 1.f, Bv = 0.f;
#pragma unroll
    for (int i = 0; i < CH; i++) {
        int row = b * LL + t0 + i;
        float g  = g_gate[(size_t)row * SS + s];
        float si = g_comb[(size_t)row * EE + DD + s];
        gl[i] = g;
        cl[i] = (1.f - g) * si;
        A  = g * A;
        Bv = g * Bv + cl[i];
    }
    sA[tid] = A; sB[tid] = Bv;
    __syncthreads();

    // inclusive Hillis-Steele scan of affine maps: combine(prev, cur) = cur ∘ prev
    for (int off = 1; off < 256; off <<= 1) {
        float cA = sA[tid], cB = sB[tid];
        float pA = 1.f, pB = 0.f;
        if (tid >= off) { pA = sA[tid - off]; pB = sB[tid - off]; }
        __syncthreads();
        sA[tid] = cA * pA;
        sB[tid] = cA * pB + cB;
        __syncthreads();
    }

    float st = (tid == 0) ? 0.f : sB[tid - 1];   // init state is 0 -> prefix value is B
#pragma unroll
    for (int i = 0; i < CH; i++) {
        int row = b * LL + t0 + i;
        st = gl[i] * st + cl[i];
        g_comb[(size_t)row * EE + DD + s] = st;
    }
    if (t0 + CH == LL)
        finals[layer * BB * SS + b * SS + s] = st;
}

// ---------------- layernorm over D=256, one block per row ----------------
__global__ void ln_kernel(const float* __restrict__ gamma, const float* __restrict__ beta) {
    __shared__ float red[8];
    const int row = blockIdx.x;
    const int tid = threadIdx.x;
    const int lane = tid & 31, warp = tid >> 5;

    float x = g_h[(size_t)row * DD + tid];

    float v = x;
#pragma unroll
    for (int off = 16; off > 0; off >>= 1) v += __shfl_xor_sync(0xffffffffu, v, off);
    if (lane == 0) red[warp] = v;
    __syncthreads();
    float tot = 0.f;
#pragma unroll
    for (int i = 0; i < 8; i++) tot += red[i];
    float mu = tot * (1.f / DD);
    float d = x - mu;
    __syncthreads();

    v = d * d;
#pragma unroll
    for (int off = 16; off > 0; off >>= 1) v += __shfl_xor_sync(0xffffffffu, v, off);
    if (lane == 0) red[warp] = v;
    __syncthreads();
    float tot2 = 0.f;
#pragma unroll
    for (int i = 0; i < 8; i++) tot2 += red[i];
    float var = tot2 * (1.f / DD);

    g_hn[(size_t)row * DD + tid] = d * rsqrtf(var + 1e-5f) * gamma[tid] + beta[tid];
}

// ---------------- launch ----------------
extern "C" void kernel_launch(void* const* d_in, const int* in_sizes, int n_in,
                              void* d_out, int out_size) {
    const int*   x_t   = (const int*)  d_in[0];
    const float* table = (const float*)d_in[1];
    const float* Wi    = (const float*)d_in[2];
    const float* bi    = (const float*)d_in[3];
    const float* Wg    = (const float*)d_in[4];
    const float* bg    = (const float*)d_in[5];
    const float* Wo    = (const float*)d_in[6];
    const float* bo    = (const float*)d_in[7];
    const float* gamma = (const float*)d_in[8];
    const float* beta  = (const float*)d_in[9];
    const float* Wc    = (const float*)d_in[10];
    const float* bc    = (const float*)d_in[11];
    const float* Wr    = (const float*)d_in[12];
    const float* br    = (const float*)d_in[13];

    float* out    = (float*)d_out;
    float* logits = out;                                   // [ROWS, VOCAB]
    float* recon  = out + (size_t)ROWS * VOCAB;            // [ROWS, DD]
    float* finals = recon + (size_t)ROWS * DD;             // [DEPTH, BB, SS]

    float *h_p = nullptr, *hn_p = nullptr, *comb_p = nullptr;
    cudaGetSymbolAddress((void**)&h_p,   g_h);
    cudaGetSymbolAddress((void**)&hn_p,  g_hn);
    cudaGetSymbolAddress((void**)&comb_p, g_comb);

    embed_kernel<<<ROWS, DD>>>(x_t, table);

    for (int i = 0; i < DEPTH; i++) {
        // combined = h @ Wi[i] + bi[i]   (4096 x 264)
        sgemm_bias_kernel<64, 64, 8, 4, 4>
            <<<dim3((EE + 63) / 64, ROWS / 64), 256>>>(
                h_p, Wi + (size_t)i * DD * EE, bi + (size_t)i * EE, comb_p,
                ROWS, EE, DD);
        // gate = sigmoid(combined @ Wg[i] + bg[i])
        gate_kernel<<<ROWS / 8, 256>>>(Wg + (size_t)i * EE * SS, bg + (size_t)i * SS);
        // recurrence: overwrite state_in slots of g_comb with states
        scan_kernel<<<BB * SS, 256>>>(finals, i);
        // h = concat(embed_part, states) @ Wo[i] + bo[i]   (4096 x 256)
        sgemm_bias_kernel<64, 64, 8, 4, 4>
            <<<dim3(DD / 64, ROWS / 64), 256>>>(
                comb_p, Wo + (size_t)i * EE * DD, bo + (size_t)i * DD, h_p,
                ROWS, DD, EE);
    }

    ln_kernel<<<ROWS, DD>>>(gamma, beta);

    // logits = hn @ Wc + bc   (4096 x 32000) -- the big one
    sgemm_bias_kernel<128, 128, 8, 8, 8>
        <<<dim3(VOCAB / 128, ROWS / 128), 256>>>(
            hn_p, Wc, bc, logits, ROWS, VOCAB, DD);

    // recon = hn @ Wr + br   (4096 x 256)
    sgemm_bias_kernel<64, 64, 8, 4, 4>
        <<<dim3(DD / 64, ROWS / 64), 256>>>(
            hn_p, Wr, br, recon, ROWS, DD, DD);
}

// round 4
// speedup vs baseline: 2.3312x; 2.3312x over previous
#include <cuda_runtime.h>
#include <math.h>
#include <stdint.h>

// ---------------- problem constants ----------------
#define BB 2
#define LL 2048
#define DD 256
#define SS 8
#define DEPTH 4
#define VOCAB 32000
#define EE (DD + SS)        // 264
#define ROWS (BB * LL)      // 4096

// ---------------- scratch (device globals; no cudaMalloc allowed) ----------------
__device__ float g_h[ROWS * DD];        // layer activations
__device__ float g_hn[ROWS * DD];       // layernorm output (exact fp32, for recon)
__device__ float g_hnt[ROWS * DD];      // layernorm output, tf32-rounded (for logits MMA)
__device__ float g_comb[ROWS * EE];     // combined / concat(embed_part, states)
__device__ float g_gate[ROWS * SS];     // gates
__device__ float g_wct[(size_t)VOCAB * DD]; // Wc transposed [V, D], tf32-rounded

// ================= helpers =================
__device__ __forceinline__ uint32_t smem_u32(const void* p) {
    uint32_t a;
    asm("{ .reg .u64 t; cvta.to.shared.u64 t, %1; cvt.u32.u64 %0, t; }" : "=r"(a) : "l"(p));
    return a;
}
__device__ __forceinline__ float tf32_rna(float x) {
    uint32_t u;
    asm("cvt.rna.tf32.f32 %0, %1;" : "=r"(u) : "f"(x));
    return __uint_as_float(u);
}
__device__ __forceinline__ void cp_async16(uint32_t saddr, const void* gptr) {
    asm volatile("cp.async.cg.shared.global [%0], [%1], 16;" :: "r"(saddr), "l"(gptr));
}
__device__ __forceinline__ void cp_async_commit() {
    asm volatile("cp.async.commit_group;");
}
template<int N>
__device__ __forceinline__ void cp_async_wait() {
    asm volatile("cp.async.wait_group %0;" :: "n"(N) : "memory");
}

// mma.sync m16n8k8 tf32: D = A*B + D  (baseline PTX, works on sm_103 target)
__device__ __forceinline__ void mma_tf32(float* d, const uint32_t* a, const uint32_t* b) {
    asm volatile(
        "mma.sync.aligned.m16n8k8.row.col.f32.tf32.tf32.f32 "
        "{%0,%1,%2,%3}, {%4,%5,%6,%7}, {%8,%9}, {%0,%1,%2,%3};"
        : "+f"(d[0]), "+f"(d[1]), "+f"(d[2]), "+f"(d[3])
        : "r"(a[0]), "r"(a[1]), "r"(a[2]), "r"(a[3]), "r"(b[0]), "r"(b[1]));
}

// ---------------- embedding gather ----------------
__global__ void embed_kernel(const int* __restrict__ x, const float* __restrict__ table) {
    int row = blockIdx.x;
    int d = threadIdx.x;
    g_h[row * DD + d] = table[(size_t)x[row] * DD + d];
}

// ---------------- Wc transpose with tf32 rounding: [D,V] -> [V,D] ----------------
__global__ void transpose_wc_kernel(const float* __restrict__ Wc) {
    __shared__ float t[32][33];
    int nb = blockIdx.x * 32;
    int kb = blockIdx.y * 32;
    int tx = threadIdx.x, ty = threadIdx.y;
    t[ty][tx] = Wc[(size_t)(kb + ty) * VOCAB + nb + tx];
    __syncthreads();
    g_wct[(size_t)(nb + ty) * DD + kb + tx] = tf32_rna(t[tx][ty]);
}

// ---------------- generic SGEMM with bias (fp32, small GEMMs) ----------------
template<int BM, int BN, int BK, int TM, int TN>
__global__ void sgemm_bias_kernel(const float* __restrict__ A,
                                  const float* __restrict__ B,
                                  const float* __restrict__ bias,
                                  float* __restrict__ C,
                                  int M, int N, int K) {
    constexpr int THREADS = (BM / TM) * (BN / TN);
    __shared__ float As[BK][BM];
    __shared__ float Bs[BK][BN];

    const int tid = threadIdx.x;
    const int tcol = tid % (BN / TN);
    const int trow = tid / (BN / TN);
    const int row0 = blockIdx.y * BM;
    const int col0 = blockIdx.x * BN;

    constexpr int A_TPR = BK / 4;
    const int aRow = tid / A_TPR;
    const int aCol = (tid % A_TPR) * 4;
    constexpr int A_RSTRIDE = THREADS / A_TPR;

    constexpr int B_TPR = BN / 4;
    const int bRow = tid / B_TPR;
    const int bCol = (tid % B_TPR) * 4;
    constexpr int B_RSTRIDE = THREADS / B_TPR;

    float acc[TM][TN];
#pragma unroll
    for (int i = 0; i < TM; i++)
#pragma unroll
        for (int j = 0; j < TN; j++) acc[i][j] = 0.f;

    float regM[TM], regN[TN];

    for (int k0 = 0; k0 < K; k0 += BK) {
#pragma unroll
        for (int r = aRow; r < BM; r += A_RSTRIDE) {
            float4 v = *(const float4*)(&A[(size_t)(row0 + r) * K + k0 + aCol]);
            As[aCol + 0][r] = v.x;
            As[aCol + 1][r] = v.y;
            As[aCol + 2][r] = v.z;
            As[aCol + 3][r] = v.w;
        }
#pragma unroll
        for (int r = bRow; r < BK; r += B_RSTRIDE) {
            float4 v = make_float4(0.f, 0.f, 0.f, 0.f);
            if (col0 + bCol < N)
                v = *(const float4*)(&B[(size_t)(k0 + r) * N + col0 + bCol]);
            *(float4*)&Bs[r][bCol] = v;
        }
        __syncthreads();

#pragma unroll
        for (int k = 0; k < BK; k++) {
#pragma unroll
            for (int i = 0; i < TM; i++) regM[i] = As[k][trow * TM + i];
#pragma unroll
            for (int j = 0; j < TN; j++) regN[j] = Bs[k][tcol * TN + j];
#pragma unroll
            for (int i = 0; i < TM; i++)
#pragma unroll
                for (int j = 0; j < TN; j++) acc[i][j] += regM[i] * regN[j];
        }
        __syncthreads();
    }

#pragma unroll
    for (int i = 0; i < TM; i++) {
        int r = row0 + trow * TM + i;
#pragma unroll
        for (int j = 0; j < TN; j += 4) {
            int c = col0 + tcol * TN + j;
            if (c < N) {
                float4 bv = *(const float4*)(&bias[c]);
                float4 o;
                o.x = acc[i][j + 0] + bv.x;
                o.y = acc[i][j + 1] + bv.y;
                o.z = acc[i][j + 2] + bv.z;
                o.w = acc[i][j + 3] + bv.w;
                *(float4*)(&C[(size_t)r * N + c]) = o;
            }
        }
    }
}

// ---------------- gate: sigmoid(combined @ Wg + bg), one warp per row ----------------
__global__ void gate_kernel(const float* __restrict__ Wg, const float* __restrict__ bg) {
    int warp = threadIdx.x >> 5;
    int lane = threadIdx.x & 31;
    int row = blockIdx.x * 8 + warp;

    float acc[SS];
#pragma unroll
    for (int s = 0; s < SS; s++) acc[s] = 0.f;

    for (int e = lane; e < EE; e += 32) {
        float a = g_comb[(size_t)row * EE + e];
        float4 w0 = *(const float4*)(Wg + (size_t)e * SS);
        float4 w1 = *(const float4*)(Wg + (size_t)e * SS + 4);
        acc[0] += a * w0.x; acc[1] += a * w0.y; acc[2] += a * w0.z; acc[3] += a * w0.w;
        acc[4] += a * w1.x; acc[5] += a * w1.y; acc[6] += a * w1.z; acc[7] += a * w1.w;
    }
#pragma unroll
    for (int s = 0; s < SS; s++)
#pragma unroll
        for (int off = 16; off > 0; off >>= 1)
            acc[s] += __shfl_down_sync(0xffffffffu, acc[s], off);

    if (lane == 0) {
#pragma unroll
        for (int s = 0; s < SS; s++) {
            float z = acc[s] + bg[s];
            g_gate[(size_t)row * SS + s] = 1.f / (1.f + expf(-z));
        }
    }
}

// ---------------- linear recurrence via affine-map prefix scan ----------------
__global__ void scan_kernel(float* __restrict__ finals, int layer) {
    __shared__ float sA[256];
    __shared__ float sB[256];
    const int b = blockIdx.x >> 3;
    const int s = blockIdx.x & 7;
    const int tid = threadIdx.x;
    constexpr int CH = LL / 256;

    const int t0 = tid * CH;
    float gl[CH], cl[CH];
    float A = 1.f, Bv = 0.f;
#pragma unroll
    for (int i = 0; i < CH; i++) {
        int row = b * LL + t0 + i;
        float g  = g_gate[(size_t)row * SS + s];
        float si = g_comb[(size_t)row * EE + DD + s];
        gl[i] = g;
        cl[i] = (1.f - g) * si;
        A  = g * A;
        Bv = g * Bv + cl[i];
    }
    sA[tid] = A; sB[tid] = Bv;
    __syncthreads();

    for (int off = 1; off < 256; off <<= 1) {
        float cA = sA[tid], cB = sB[tid];
        float pA = 1.f, pB = 0.f;
        if (tid >= off) { pA = sA[tid - off]; pB = sB[tid - off]; }
        __syncthreads();
        sA[tid] = cA * pA;
        sB[tid] = cA * pB + cB;
        __syncthreads();
    }

    float st = (tid == 0) ? 0.f : sB[tid - 1];
#pragma unroll
    for (int i = 0; i < CH; i++) {
        int row = b * LL + t0 + i;
        st = gl[i] * st + cl[i];
        g_comb[(size_t)row * EE + DD + s] = st;
    }
    if (t0 + CH == LL)
        finals[layer * BB * SS + b * SS + s] = st;
}

// ---------------- layernorm over D=256, one block per row ----------------
__global__ void ln_kernel(const float* __restrict__ gamma, const float* __restrict__ beta) {
    __shared__ float red[8];
    const int row = blockIdx.x;
    const int tid = threadIdx.x;
    const int lane = tid & 31, warp = tid >> 5;

    float x = g_h[(size_t)row * DD + tid];

    float v = x;
#pragma unroll
    for (int off = 16; off > 0; off >>= 1) v += __shfl_xor_sync(0xffffffffu, v, off);
    if (lane == 0) red[warp] = v;
    __syncthreads();
    float tot = 0.f;
#pragma unroll
    for (int i = 0; i < 8; i++) tot += red[i];
    float mu = tot * (1.f / DD);
    float d = x - mu;
    __syncthreads();

    v = d * d;
#pragma unroll
    for (int off = 16; off > 0; off >>= 1) v += __shfl_xor_sync(0xffffffffu, v, off);
    if (lane == 0) red[warp] = v;
    __syncthreads();
    float tot2 = 0.f;
#pragma unroll
    for (int i = 0; i < 8; i++) tot2 += red[i];
    float var = tot2 * (1.f / DD);

    float y = d * rsqrtf(var + 1e-5f) * gamma[tid] + beta[tid];
    g_hn[(size_t)row * DD + tid] = y;
    g_hnt[(size_t)row * DD + tid] = tf32_rna(y);
}

// ================= tf32 mma.sync logits GEMM =================
// C[4096, 32000] = A[4096,256] @ WcT[32000,256]^T + bc
// CTA tile 128x128, 8 warps (4 in M x 2 in N), warp tile 32x64 (2 x 8 mma tiles),
// k chunks of 32 floats, cp.async double-buffered.
#define GM_M 128
#define GM_N 128
#define GM_KC 32
#define GM_NCHUNK (DD / GM_KC)     // 8
#define PITCH 36                   // floats per smem row: (4*r+c)%32 distinct -> no bank conflicts
#define ABUF (GM_M * PITCH)        // 4608 floats = 18432 B per buffer
#define SMEM_BYTES (4 * ABUF * 4)  // A0,A1,B0,B1 = 73728 B

__global__ void __launch_bounds__(256)
logits_mma_kernel(const float* __restrict__ bc, float* __restrict__ C) {
    extern __shared__ float sm[];
    const int tid = threadIdx.x;
    const int wid = tid >> 5;
    const int lane = tid & 31;
    const int warp_m = wid & 3;     // 0..3
    const int warp_n = wid >> 2;    // 0..1
    const int row0 = blockIdx.y * GM_M;
    const int col0 = blockIdx.x * GM_N;

    const uint32_t s_base = smem_u32(sm);
    // byte offsets of the 4 buffers
    const uint32_t aOff[2] = { 0u, (uint32_t)(ABUF * 4) };
    const uint32_t bOff[2] = { (uint32_t)(2 * ABUF * 4), (uint32_t)(3 * ABUF * 4) };

    float acc[2][8][4];
#pragma unroll
    for (int mt = 0; mt < 2; mt++)
#pragma unroll
        for (int nt = 0; nt < 8; nt++)
#pragma unroll
            for (int i = 0; i < 4; i++) acc[mt][nt][i] = 0.f;

    // ---- chunk loader: 128 rows x 32 floats for A and B, 16B per cp.async ----
    auto load_chunk = [&](int c, int buf) {
#pragma unroll
        for (int t = 0; t < 4; t++) {
            int idx = tid + t * 256;        // 0..1023
            int m = idx >> 3;
            int k16 = idx & 7;
            cp_async16(s_base + aOff[buf] + (uint32_t)(m * (PITCH * 4) + k16 * 16),
                       &g_hnt[(size_t)(row0 + m) * DD + c * GM_KC + k16 * 4]);
        }
#pragma unroll
        for (int t = 0; t < 4; t++) {
            int idx = tid + t * 256;
            int n = idx >> 3;
            int k16 = idx & 7;
            cp_async16(s_base + bOff[buf] + (uint32_t)(n * (PITCH * 4) + k16 * 16),
                       &g_wct[(size_t)(col0 + n) * DD + c * GM_KC + k16 * 4]);
        }
        cp_async_commit();
    };

    load_chunk(0, 0);

    const int ar = warp_m * 32 + (lane >> 2);   // A fragment base row
    const int bcol = warp_n * 64 + (lane >> 2); // B fragment base n-row
    const int kl = lane & 3;

    for (int c = 0; c < GM_NCHUNK; c++) {
        if (c + 1 < GM_NCHUNK) {
            load_chunk(c + 1, (c + 1) & 1);
            cp_async_wait<1>();
        } else {
            cp_async_wait<0>();
        }
        __syncthreads();

        const float* Ab = sm + (c & 1) * ABUF;
        const float* Bb = sm + 2 * ABUF + (c & 1) * ABUF;

#pragma unroll
        for (int ks = 0; ks < 4; ks++) {
            const int k0 = ks * 8 + kl;
            uint32_t afr[2][4];
#pragma unroll
            for (int mt = 0; mt < 2; mt++) {
                int r = ar + mt * 16;
                afr[mt][0] = __float_as_uint(Ab[r * PITCH + k0]);
                afr[mt][1] = __float_as_uint(Ab[(r + 8) * PITCH + k0]);
                afr[mt][2] = __float_as_uint(Ab[r * PITCH + k0 + 4]);
                afr[mt][3] = __float_as_uint(Ab[(r + 8) * PITCH + k0 + 4]);
            }
            uint32_t bfr[8][2];
#pragma unroll
            for (int nt = 0; nt < 8; nt++) {
                int n = bcol + nt * 8;
                bfr[nt][0] = __float_as_uint(Bb[n * PITCH + k0]);
                bfr[nt][1] = __float_as_uint(Bb[n * PITCH + k0 + 4]);
            }
#pragma unroll
            for (int mt = 0; mt < 2; mt++)
#pragma unroll
                for (int nt = 0; nt < 8; nt++)
                    mma_tf32(acc[mt][nt], afr[mt], bfr[nt]);
        }
        __syncthreads();
    }

    // ---- epilogue: add bias, write float2 per fragment row ----
#pragma unroll
    for (int nt = 0; nt < 8; nt++) {
        int cc = col0 + warp_n * 64 + nt * 8 + (lane & 3) * 2;
        float2 bv = *(const float2*)(&bc[cc]);
#pragma unroll
        for (int mt = 0; mt < 2; mt++) {
            int r = row0 + warp_m * 32 + mt * 16 + (lane >> 2);
            float2 v0 = make_float2(acc[mt][nt][0] + bv.x, acc[mt][nt][1] + bv.y);
            float2 v1 = make_float2(acc[mt][nt][2] + bv.x, acc[mt][nt][3] + bv.y);
            *(float2*)(&C[(size_t)r * VOCAB + cc]) = v0;
            *(float2*)(&C[(size_t)(r + 8) * VOCAB + cc]) = v1;
        }
    }
}

// ---------------- launch ----------------
extern "C" void kernel_launch(void* const* d_in, const int* in_sizes, int n_in,
                              void* d_out, int out_size) {
    const int*   x_t   = (const int*)  d_in[0];
    const float* table = (const float*)d_in[1];
    const float* Wi    = (const float*)d_in[2];
    const float* bi    = (const float*)d_in[3];
    const float* Wg    = (const float*)d_in[4];
    const float* bg    = (const float*)d_in[5];
    const float* Wo    = (const float*)d_in[6];
    const float* bo    = (const float*)d_in[7];
    const float* gamma = (const float*)d_in[8];
    const float* beta  = (const float*)d_in[9];
    const float* Wc    = (const float*)d_in[10];
    const float* bc    = (const float*)d_in[11];
    const float* Wr    = (const float*)d_in[12];
    const float* br    = (const float*)d_in[13];

    float* out    = (float*)d_out;
    float* logits = out;
    float* recon  = out + (size_t)ROWS * VOCAB;
    float* finals = recon + (size_t)ROWS * DD;

    float *h_p = nullptr, *hn_p = nullptr, *comb_p = nullptr;
    cudaGetSymbolAddress((void**)&h_p,   g_h);
    cudaGetSymbolAddress((void**)&hn_p,  g_hn);
    cudaGetSymbolAddress((void**)&comb_p, g_comb);

    cudaFuncSetAttribute(logits_mma_kernel,
                         cudaFuncAttributeMaxDynamicSharedMemorySize, SMEM_BYTES);

    embed_kernel<<<ROWS, DD>>>(x_t, table);
    transpose_wc_kernel<<<dim3(VOCAB / 32, DD / 32), dim3(32, 32)>>>(Wc);

    for (int i = 0; i < DEPTH; i++) {
        sgemm_bias_kernel<64, 64, 8, 4, 4>
            <<<dim3((EE + 63) / 64, ROWS / 64), 256>>>(
                h_p, Wi + (size_t)i * DD * EE, bi + (size_t)i * EE, comb_p,
                ROWS, EE, DD);
        gate_kernel<<<ROWS / 8, 256>>>(Wg + (size_t)i * EE * SS, bg + (size_t)i * SS);
        scan_kernel<<<BB * SS, 256>>>(finals, i);
        sgemm_bias_kernel<64, 64, 8, 4, 4>
            <<<dim3(DD / 64, ROWS / 64), 256>>>(
                comb_p, Wo + (size_t)i * EE * DD, bo + (size_t)i * DD, h_p,
                ROWS, DD, EE);
    }

    ln_kernel<<<ROWS, DD>>>(gamma, beta);

    // logits via mma.sync tf32 (tensor pipe, baseline PTX)
    logits_mma_kernel<<<dim3(VOCAB / GM_N, ROWS / GM_M), 256, SMEM_BYTES>>>(bc, logits);

    // recon = hn @ Wr + br (fp32 exact)
    sgemm_bias_kernel<64, 64, 8, 4, 4>
        <<<dim3(DD / 64, ROWS / 64), 256>>>(
            hn_p, Wr, br, recon, ROWS, DD, DD);
}

// round 6
// speedup vs baseline: 3.1210x; 1.3388x over previous
#include <cuda_runtime.h>
#include <cuda_fp16.h>
#include <math.h>
#include <stdint.h>

// ---------------- problem constants ----------------
#define BB 2
#define LL 2048
#define DD 256
#define SS 8
#define DEPTH 4
#define VOCAB 32000
#define EE (DD + SS)        // 264
#define ROWS (BB * LL)      // 4096

// ---------------- scratch (device globals; no cudaMalloc allowed) ----------------
__device__ float g_h[ROWS * DD];        // layer activations
__device__ float g_hn[ROWS * DD];       // layernorm output (exact fp32, for recon)
__device__ __align__(16) __half g_hnh[ROWS * DD];   // layernorm output, fp16 (logits MMA A)
__device__ float g_comb[ROWS * EE];     // combined / concat(embed_part, states)
__device__ float g_gate[ROWS * SS];     // gates
__device__ __align__(16) __half g_wch[(size_t)DD * VOCAB]; // Wc in fp16, native [D][V] layout

// ================= helpers =================
__device__ __forceinline__ uint32_t smem_u32(const void* p) {
    uint32_t a;
    asm("{ .reg .u64 t; cvta.to.shared.u64 t, %1; cvt.u32.u64 %0, t; }" : "=r"(a) : "l"(p));
    return a;
}
__device__ __forceinline__ void cp_async16(uint32_t saddr, const void* gptr) {
    asm volatile("cp.async.cg.shared.global [%0], [%1], 16;" :: "r"(saddr), "l"(gptr));
}
__device__ __forceinline__ void cp_async_commit() {
    asm volatile("cp.async.commit_group;");
}
template<int N>
__device__ __forceinline__ void cp_async_wait() {
    asm volatile("cp.async.wait_group %0;" :: "n"(N) : "memory");
}

// mma.sync m16n8k16 fp16 -> fp32 accum (baseline PTX, sm_80+)
__device__ __forceinline__ void mma_f16(float* d, const uint32_t* a, const uint32_t* b) {
    asm volatile(
        "mma.sync.aligned.m16n8k16.row.col.f32.f16.f16.f32 "
        "{%0,%1,%2,%3}, {%4,%5,%6,%7}, {%8,%9}, {%0,%1,%2,%3};"
        : "+f"(d[0]), "+f"(d[1]), "+f"(d[2]), "+f"(d[3])
        : "r"(a[0]), "r"(a[1]), "r"(a[2]), "r"(a[3]), "r"(b[0]), "r"(b[1]));
}
__device__ __forceinline__ void ldsm_x4(uint32_t* r, uint32_t addr) {
    asm volatile("ldmatrix.sync.aligned.m8n8.x4.shared.b16 {%0,%1,%2,%3}, [%4];"
                 : "=r"(r[0]), "=r"(r[1]), "=r"(r[2]), "=r"(r[3]) : "r"(addr));
}
__device__ __forceinline__ void ldsm_x4_t(uint32_t* r, uint32_t addr) {
    asm volatile("ldmatrix.sync.aligned.m8n8.x4.trans.shared.b16 {%0,%1,%2,%3}, [%4];"
                 : "=r"(r[0]), "=r"(r[1]), "=r"(r[2]), "=r"(r[3]) : "r"(addr));
}

#define SW128(x) ((x) ^ (((x) >> 3) & 0x70))

// ---------------- embedding gather ----------------
__global__ void embed_kernel(const int* __restrict__ x, const float* __restrict__ table) {
    int row = blockIdx.x;
    int d = threadIdx.x;
    g_h[row * DD + d] = table[(size_t)x[row] * DD + d];
}

// ---------------- Wc fp32 -> fp16, same [D][V] layout ----------------
__global__ void convert_wc_kernel(const float* __restrict__ Wc) {
    size_t i = ((size_t)blockIdx.x * 256 + threadIdx.x) * 4;
    float4 v = *(const float4*)(Wc + i);
    __half2* o = (__half2*)(g_wch + i);
    o[0] = __floats2half2_rn(v.x, v.y);
    o[1] = __floats2half2_rn(v.z, v.w);
}

// ---------------- generic SGEMM with bias (fp32, small GEMMs) ----------------
template<int BM, int BN, int BK, int TM, int TN>
__global__ void sgemm_bias_kernel(const float* __restrict__ A,
                                  const float* __restrict__ B,
                                  const float* __restrict__ bias,
                                  float* __restrict__ C,
                                  int M, int N, int K) {
    constexpr int THREADS = (BM / TM) * (BN / TN);
    __shared__ float As[BK][BM];
    __shared__ float Bs[BK][BN];

    const int tid = threadIdx.x;
    const int tcol = tid % (BN / TN);
    const int trow = tid / (BN / TN);
    const int row0 = blockIdx.y * BM;
    const int col0 = blockIdx.x * BN;

    constexpr int A_TPR = BK / 4;
    const int aRow = tid / A_TPR;
    const int aCol = (tid % A_TPR) * 4;
    constexpr int A_RSTRIDE = THREADS / A_TPR;

    constexpr int B_TPR = BN / 4;
    const int bRow = tid / B_TPR;
    const int bCol = (tid % B_TPR) * 4;
    constexpr int B_RSTRIDE = THREADS / B_TPR;

    float acc[TM][TN];
#pragma unroll
    for (int i = 0; i < TM; i++)
#pragma unroll
        for (int j = 0; j < TN; j++) acc[i][j] = 0.f;

    float regM[TM], regN[TN];

    for (int k0 = 0; k0 < K; k0 += BK) {
#pragma unroll
        for (int r = aRow; r < BM; r += A_RSTRIDE) {
            float4 v = *(const float4*)(&A[(size_t)(row0 + r) * K + k0 + aCol]);
            As[aCol + 0][r] = v.x;
            As[aCol + 1][r] = v.y;
            As[aCol + 2][r] = v.z;
            As[aCol + 3][r] = v.w;
        }
#pragma unroll
        for (int r = bRow; r < BK; r += B_RSTRIDE) {
            float4 v = make_float4(0.f, 0.f, 0.f, 0.f);
            if (col0 + bCol < N)
                v = *(const float4*)(&B[(size_t)(k0 + r) * N + col0 + bCol]);
            *(float4*)&Bs[r][bCol] = v;
        }
        __syncthreads();

#pragma unroll
        for (int k = 0; k < BK; k++) {
#pragma unroll
            for (int i = 0; i < TM; i++) regM[i] = As[k][trow * TM + i];
#pragma unroll
            for (int j = 0; j < TN; j++) regN[j] = Bs[k][tcol * TN + j];
#pragma unroll
            for (int i = 0; i < TM; i++)
#pragma unroll
                for (int j = 0; j < TN; j++) acc[i][j] += regM[i] * regN[j];
        }
        __syncthreads();
    }

#pragma unroll
    for (int i = 0; i < TM; i++) {
        int r = row0 + trow * TM + i;
#pragma unroll
        for (int j = 0; j < TN; j += 4) {
            int c = col0 + tcol * TN + j;
            if (c < N) {
                float4 bv = *(const float4*)(&bias[c]);
                float4 o;
                o.x = acc[i][j + 0] + bv.x;
                o.y = acc[i][j + 1] + bv.y;
                o.z = acc[i][j + 2] + bv.z;
                o.w = acc[i][j + 3] + bv.w;
                *(float4*)(&C[(size_t)r * N + c]) = o;
            }
        }
    }
}

// ---------------- gate: sigmoid(combined @ Wg + bg), one warp per row ----------------
__global__ void gate_kernel(const float* __restrict__ Wg, const float* __restrict__ bg) {
    int warp = threadIdx.x >> 5;
    int lane = threadIdx.x & 31;
    int row = blockIdx.x * 8 + warp;

    float acc[SS];
#pragma unroll
    for (int s = 0; s < SS; s++) acc[s] = 0.f;

    for (int e = lane; e < EE; e += 32) {
        float a = g_comb[(size_t)row * EE + e];
        float4 w0 = *(const float4*)(Wg + (size_t)e * SS);
        float4 w1 = *(const float4*)(Wg + (size_t)e * SS + 4);
        acc[0] += a * w0.x; acc[1] += a * w0.y; acc[2] += a * w0.z; acc[3] += a * w0.w;
        acc[4] += a * w1.x; acc[5] += a * w1.y; acc[6] += a * w1.z; acc[7] += a * w1.w;
    }
#pragma unroll
    for (int s = 0; s < SS; s++)
#pragma unroll
        for (int off = 16; off > 0; off >>= 1)
            acc[s] += __shfl_down_sync(0xffffffffu, acc[s], off);

    if (lane == 0) {
#pragma unroll
        for (int s = 0; s < SS; s++) {
            float z = acc[s] + bg[s];
            g_gate[(size_t)row * SS + s] = 1.f / (1.f + expf(-z));
        }
    }
}

// ---------------- linear recurrence via affine-map prefix scan ----------------
__global__ void scan_kernel(float* __restrict__ finals, int layer) {
    __shared__ float sA[256];
    __shared__ float sB[256];
    const int b = blockIdx.x >> 3;
    const int s = blockIdx.x & 7;
    const int tid = threadIdx.x;
    constexpr int CH = LL / 256;

    const int t0 = tid * CH;
    float gl[CH], cl[CH];
    float A = 1.f, Bv = 0.f;
#pragma unroll
    for (int i = 0; i < CH; i++) {
        int row = b * LL + t0 + i;
        float g  = g_gate[(size_t)row * SS + s];
        float si = g_comb[(size_t)row * EE + DD + s];
        gl[i] = g;
        cl[i] = (1.f - g) * si;
        A  = g * A;
        Bv = g * Bv + cl[i];
    }
    sA[tid] = A; sB[tid] = Bv;
    __syncthreads();

    for (int off = 1; off < 256; off <<= 1) {
        float cA = sA[tid], cB = sB[tid];
        float pA = 1.f, pB = 0.f;
        if (tid >= off) { pA = sA[tid - off]; pB = sB[tid - off]; }
        __syncthreads();
        sA[tid] = cA * pA;
        sB[tid] = cA * pB + cB;
        __syncthreads();
    }

    float st = (tid == 0) ? 0.f : sB[tid - 1];
#pragma unroll
    for (int i = 0; i < CH; i++) {
        int row = b * LL + t0 + i;
        st = gl[i] * st + cl[i];
        g_comb[(size_t)row * EE + DD + s] = st;
    }
    if (t0 + CH == LL)
        finals[layer * BB * SS + b * SS + s] = st;
}

// ---------------- layernorm over D=256, one block per row ----------------
__global__ void ln_kernel(const float* __restrict__ gamma, const float* __restrict__ beta) {
    __shared__ float red[8];
    const int row = blockIdx.x;
    const int tid = threadIdx.x;
    const int lane = tid & 31, warp = tid >> 5;

    float x = g_h[(size_t)row * DD + tid];

    float v = x;
#pragma unroll
    for (int off = 16; off > 0; off >>= 1) v += __shfl_xor_sync(0xffffffffu, v, off);
    if (lane == 0) red[warp] = v;
    __syncthreads();
    float tot = 0.f;
#pragma unroll
    for (int i = 0; i < 8; i++) tot += red[i];
    float mu = tot * (1.f / DD);
    float d = x - mu;
    __syncthreads();

    v = d * d;
#pragma unroll
    for (int off = 16; off > 0; off >>= 1) v += __shfl_xor_sync(0xffffffffu, v, off);
    if (lane == 0) red[warp] = v;
    __syncthreads();
    float tot2 = 0.f;
#pragma unroll
    for (int i = 0; i < 8; i++) tot2 += red[i];
    float var = tot2 * (1.f / DD);

    float y = d * rsqrtf(var + 1e-5f) * gamma[tid] + beta[tid];
    g_hn[(size_t)row * DD + tid] = y;
    g_hnh[(size_t)row * DD + tid] = __float2half(y);
}

// ================= fp16 mma.sync logits GEMM =================
// C[4096, 32000] = A[4096,256] @ Wc[256,32000] + bc
// A smem: [m][k] 128x64 halves, SW128 swizzle. B smem: [k][n] 64x128 halves,
// per-128B-group XOR swizzle. ldmatrix.x4 (A) / .x4.trans (B).
// CTA 128x128, 8 warps (4M x 2N), warp tile 32x64 (2 x 8 mma tiles), K chunks of 64.
#define GM_M 128
#define GM_N 128
#define GM_KC 64
#define GM_NCHUNK (DD / GM_KC)          // 4
#define ABUF_BYTES (GM_M * GM_KC * 2)   // 16384
#define BBUF_BYTES (GM_KC * GM_N * 2)   // 16384
#define SMEM_BYTES (2 * (ABUF_BYTES + BBUF_BYTES))  // 65536

__global__ void __launch_bounds__(256)
logits_mma_kernel(const float* __restrict__ bc, float* __restrict__ C) {
    extern __shared__ char sm[];
    const int tid = threadIdx.x;
    const int wid = tid >> 5;
    const int lane = tid & 31;
    const int warp_m = wid & 3;     // 0..3
    const int warp_n = wid >> 2;    // 0..1
    const int row0 = blockIdx.y * GM_M;
    const int col0 = blockIdx.x * GM_N;

    const uint32_t s_base = smem_u32(sm);
    const uint32_t aOff[2] = { 0u, (uint32_t)ABUF_BYTES };
    const uint32_t bOff[2] = { (uint32_t)(2 * ABUF_BYTES),
                               (uint32_t)(2 * ABUF_BYTES + BBUF_BYTES) };

    float acc[2][8][4];
#pragma unroll
    for (int mt = 0; mt < 2; mt++)
#pragma unroll
        for (int nt = 0; nt < 8; nt++)
#pragma unroll
            for (int i = 0; i < 4; i++) acc[mt][nt][i] = 0.f;

    // ---- chunk loader ----
    // A: 128 m-rows x 64 k halves (128B rows), SW128 swizzle. 1024 x 16B chunks.
    // B: 64 k-rows x 128 n halves (256B rows = 2 x 128B groups), XOR-(k&7) swizzle. 1024 chunks.
    auto load_chunk = [&](int c, int buf) {
#pragma unroll
        for (int t = 0; t < 4; t++) {
            int idx = tid + t * 256;
            int m = idx >> 3;
            int c16 = idx & 7;
            cp_async16(s_base + aOff[buf] + (uint32_t)SW128(m * 128 + c16 * 16),
                       &g_hnh[(size_t)(row0 + m) * DD + c * GM_KC + c16 * 8]);
        }
#pragma unroll
        for (int t = 0; t < 4; t++) {
            int idx = tid + t * 256;
            int k = idx >> 4;
            int c16 = idx & 15;
            int group = c16 >> 3;
            int w = (c16 & 7) ^ (k & 7);
            cp_async16(s_base + bOff[buf] + (uint32_t)(k * 256 + group * 128 + w * 16),
                       &g_wch[(size_t)(c * GM_KC + k) * VOCAB + col0 + c16 * 8]);
        }
        cp_async_commit();
    };

    load_chunk(0, 0);

    for (int c = 0; c < GM_NCHUNK; c++) {
        if (c + 1 < GM_NCHUNK) {
            load_chunk(c + 1, (c + 1) & 1);
            cp_async_wait<1>();
        } else {
            cp_async_wait<0>();
        }
        __syncthreads();

        const uint32_t sA = s_base + aOff[c & 1];
        const uint32_t sB = s_base + bOff[c & 1];

#pragma unroll
        for (int ks = 0; ks < GM_KC / 16; ks++) {    // 4 k16-steps
            // A fragments: 2 ldmatrix.x4 (one per 16-row tile)
            uint32_t afr[2][4];
#pragma unroll
            for (int mt = 0; mt < 2; mt++) {
                int r = warp_m * 32 + mt * 16 + (lane & 15);
                int cb = ks * 32 + (lane >> 4) * 16;     // k byte offset within row
                ldsm_x4(afr[mt], sA + (uint32_t)SW128(r * 128 + cb));
            }
            // B fragments: 4 ldmatrix.x4.trans, each covers 2 n-tiles
            uint32_t bfr[8][2];
#pragma unroll
            for (int p = 0; p < 4; p++) {
                int k = ks * 16 + ((lane >> 3) & 1) * 8 + (lane & 7);
                int n = warp_n * 64 + p * 16 + (lane >> 4) * 8;
                int c16 = n >> 3;
                int group = c16 >> 3;
                int w = (c16 & 7) ^ (k & 7);
                uint32_t tmp[4];
                ldsm_x4_t(tmp, sB + (uint32_t)(k * 256 + group * 128 + w * 16));
                bfr[p * 2 + 0][0] = tmp[0]; bfr[p * 2 + 0][1] = tmp[1];
                bfr[p * 2 + 1][0] = tmp[2]; bfr[p * 2 + 1][1] = tmp[3];
            }
#pragma unroll
            for (int mt = 0; mt < 2; mt++)
#pragma unroll
                for (int nt = 0; nt < 8; nt++)
                    mma_f16(acc[mt][nt], afr[mt], bfr[nt]);
        }
        __syncthreads();
    }

    // ---- epilogue: add bias, write float2 per fragment row ----
#pragma unroll
    for (int nt = 0; nt < 8; nt++) {
        int cc = col0 + warp_n * 64 + nt * 8 + (lane & 3) * 2;
        float2 bv = *(const float2*)(&bc[cc]);
#pragma unroll
        for (int mt = 0; mt < 2; mt++) {
            int r = row0 + warp_m * 32 + mt * 16 + (lane >> 2);
            float2 v0 = make_float2(acc[mt][nt][0] + bv.x, acc[mt][nt][1] + bv.y);
            float2 v1 = make_float2(acc[mt][nt][2] + bv.x, acc[mt][nt][3] + bv.y);
            *(float2*)(&C[(size_t)r * VOCAB + cc]) = v0;
            *(float2*)(&C[(size_t)(r + 8) * VOCAB + cc]) = v1;
        }
    }
}

// ---------------- launch ----------------
extern "C" void kernel_launch(void* const* d_in, const int* in_sizes, int n_in,
                              void* d_out, int out_size) {
    const int*   x_t   = (const int*)  d_in[0];
    const float* table = (const float*)d_in[1];
    const float* Wi    = (const float*)d_in[2];
    const float* bi    = (const float*)d_in[3];
    const float* Wg    = (const float*)d_in[4];
    const float* bg    = (const float*)d_in[5];
    const float* Wo    = (const float*)d_in[6];
    const float* bo    = (const float*)d_in[7];
    const float* gamma = (const float*)d_in[8];
    const float* beta  = (const float*)d_in[9];
    const float* Wc    = (const float*)d_in[10];
    const float* bc    = (const float*)d_in[11];
    const float* Wr    = (const float*)d_in[12];
    const float* br    = (const float*)d_in[13];

    float* out    = (float*)d_out;
    float* logits = out;
    float* recon  = out + (size_t)ROWS * VOCAB;
    float* finals = recon + (size_t)ROWS * DD;

    float *h_p = nullptr, *hn_p = nullptr, *comb_p = nullptr;
    cudaGetSymbolAddress((void**)&h_p,   g_h);
    cudaGetSymbolAddress((void**)&hn_p,  g_hn);
    cudaGetSymbolAddress((void**)&comb_p, g_comb);

    cudaFuncSetAttribute(logits_mma_kernel,
                         cudaFuncAttributeMaxDynamicSharedMemorySize, SMEM_BYTES);

    embed_kernel<<<ROWS, DD>>>(x_t, table);
    convert_wc_kernel<<<(DD * VOCAB) / 1024, 256>>>(Wc);

    for (int i = 0; i < DEPTH; i++) {
        sgemm_bias_kernel<64, 64, 8, 4, 4>
            <<<dim3((EE + 63) / 64, ROWS / 64), 256>>>(
                h_p, Wi + (size_t)i * DD * EE, bi + (size_t)i * EE, comb_p,
                ROWS, EE, DD);
        gate_kernel<<<ROWS / 8, 256>>>(Wg + (size_t)i * EE * SS, bg + (size_t)i * SS);
        scan_kernel<<<BB * SS, 256>>>(finals, i);
        sgemm_bias_kernel<64, 64, 8, 4, 4>
            <<<dim3(DD / 64, ROWS / 64), 256>>>(
                comb_p, Wo + (size_t)i * EE * DD, bo + (size_t)i * DD, h_p,
                ROWS, DD, EE);
    }

    ln_kernel<<<ROWS, DD>>>(gamma, beta);

    // logits via fp16 mma.sync m16n8k16 (tensor pipe, baseline PTX)
    logits_mma_kernel<<<dim3(VOCAB / GM_N, ROWS / GM_M), 256, SMEM_BYTES>>>(bc, logits);

    // recon = hn @ Wr + br (fp32 exact)
    sgemm_bias_kernel<64, 64, 8, 4, 4>
        <<<dim3(DD / 64, ROWS / 64), 256>>>(
            hn_p, Wr, br, recon, ROWS, DD, DD);
}

// round 9
// speedup vs baseline: 3.3629x; 1.0775x over previous
#include <cuda_runtime.h>
#include <cuda_fp16.h>
#include <math.h>
#include <stdint.h>

// ---------------- problem constants ----------------
#define BB 2
#define LL 2048
#define DD 256
#define SS 8
#define DEPTH 4
#define VOCAB 32000
#define EE (DD + SS)        // 264
#define ROWS (BB * LL)      // 4096

// ---------------- scratch (device globals; no cudaMalloc allowed) ----------------
__device__ __align__(16) float g_h[ROWS * DD];        // layer activations (ping)
__device__ __align__(16) float g_h2[ROWS * DD];       // layer activations (pong)
__device__ __align__(16) float g_hn[ROWS * DD];       // layernorm output (fp32, for recon)
__device__ __align__(16) __half g_hnh[ROWS * DD];     // layernorm output fp16 (logits A)
__device__ __align__(16) float g_sg[ROWS * 16];       // per-row [state_in(8) | gate_pre(8)]
__device__ __align__(16) float g_states[ROWS * SS];   // scan output states
__device__ __align__(16) float g_wsg[DEPTH * DD * 16];    // [Wi2 | Wi@Wg] per layer
__device__ float g_bsg[DEPTH * 16];
__device__ __align__(16) float g_wcat[DEPTH * EE * DD];   // [Wi1@Wo1 ; Wo2] per layer
__device__ float g_bcat[DEPTH * DD];                      // bi1@Wo1 + bo
__device__ __align__(16) __half g_wch[(size_t)DD * VOCAB]; // Wc fp16, native [D][V]

// ================= helpers =================
__device__ __forceinline__ uint32_t smem_u32(const void* p) {
    uint32_t a;
    asm("{ .reg .u64 t; cvta.to.shared.u64 t, %1; cvt.u32.u64 %0, t; }" : "=r"(a) : "l"(p));
    return a;
}
__device__ __forceinline__ void cp_async16(uint32_t saddr, const void* gptr) {
    asm volatile("cp.async.cg.shared.global [%0], [%1], 16;" :: "r"(saddr), "l"(gptr));
}
__device__ __forceinline__ void cp_async_commit() {
    asm volatile("cp.async.commit_group;");
}
template<int N>
__device__ __forceinline__ void cp_async_wait() {
    asm volatile("cp.async.wait_group %0;" :: "n"(N) : "memory");
}
__device__ __forceinline__ void mma_f16(float* d, const uint32_t* a, const uint32_t* b) {
    asm volatile(
        "mma.sync.aligned.m16n8k16.row.col.f32.f16.f16.f32 "
        "{%0,%1,%2,%3}, {%4,%5,%6,%7}, {%8,%9}, {%0,%1,%2,%3};"
        : "+f"(d[0]), "+f"(d[1]), "+f"(d[2]), "+f"(d[3])
        : "r"(a[0]), "r"(a[1]), "r"(a[2]), "r"(a[3]), "r"(b[0]), "r"(b[1]));
}
__device__ __forceinline__ void ldsm_x4(uint32_t* r, uint32_t addr) {
    asm volatile("ldmatrix.sync.aligned.m8n8.x4.shared.b16 {%0,%1,%2,%3}, [%4];"
                 : "=r"(r[0]), "=r"(r[1]), "=r"(r[2]), "=r"(r[3]) : "r"(addr));
}
__device__ __forceinline__ void ldsm_x4_t(uint32_t* r, uint32_t addr) {
    asm volatile("ldmatrix.sync.aligned.m8n8.x4.trans.shared.b16 {%0,%1,%2,%3}, [%4];"
                 : "=r"(r[0]), "=r"(r[1]), "=r"(r[2]), "=r"(r[3]) : "r"(addr));
}
#define SW128(x) ((x) ^ (((x) >> 3) & 0x70))

// ---------------- embedding gather ----------------
__global__ void embed_kernel(const int* __restrict__ x, const float* __restrict__ table) {
    int row = blockIdx.x;
    int d = threadIdx.x;
    g_h[row * DD + d] = table[(size_t)x[row] * DD + d];
}

// ---------------- Wc fp32 -> fp16 ----------------
__global__ void convert_wc_kernel(const float* __restrict__ Wc) {
    size_t i = ((size_t)blockIdx.x * 256 + threadIdx.x) * 4;
    float4 v = *(const float4*)(Wc + i);
    __half2* o = (__half2*)(g_wch + i);
    o[0] = __floats2half2_rn(v.x, v.y);
    o[1] = __floats2half2_rn(v.z, v.w);
}

// ---------------- precompute: Wsg = [Wi2 | Wi@Wg], bsg ----------------
__global__ void wf_kernel(const float* __restrict__ Wi, const float* __restrict__ bi,
                          const float* __restrict__ Wg, const float* __restrict__ bg) {
    int i = blockIdx.x;   // layer
    int d = threadIdx.x;  // 0..255
    const float* wi = Wi + (size_t)i * DD * EE;
    const float* wg = Wg + (size_t)i * EE * SS;
    float f[8] = {0.f, 0.f, 0.f, 0.f, 0.f, 0.f, 0.f, 0.f};
    for (int e = 0; e < EE; e++) {
        float a = wi[d * EE + e];
        float4 w0 = *(const float4*)(wg + e * 8);
        float4 w1 = *(const float4*)(wg + e * 8 + 4);
        f[0] += a * w0.x; f[1] += a * w0.y; f[2] += a * w0.z; f[3] += a * w0.w;
        f[4] += a * w1.x; f[5] += a * w1.y; f[6] += a * w1.z; f[7] += a * w1.w;
    }
    float* dst = g_wsg + ((size_t)i * DD + d) * 16;
#pragma unroll
    for (int s = 0; s < 8; s++) dst[s] = wi[d * EE + DD + s];   // Wi2
#pragma unroll
    for (int s = 0; s < 8; s++) dst[8 + s] = f[s];              // Wi@Wg
    if (d < 8) {
        g_bsg[i * 16 + d] = bi[(size_t)i * EE + DD + d];
    } else if (d < 16) {
        int s = d - 8;
        float bv = bg[i * SS + s];
        for (int e = 0; e < EE; e++) bv += bi[(size_t)i * EE + e] * wg[e * 8 + s];
        g_bsg[i * 16 + d] = bv;
    }
}

// ---------------- precompute: Wcat rows 256..263 (Wo2) + bcat ----------------
__global__ void wcat_tail_kernel(const float* __restrict__ Wo, const float* __restrict__ bi,
                                 const float* __restrict__ bo) {
    int i = blockIdx.x;
    int n = threadIdx.x;  // 0..255
    const float* wo = Wo + (size_t)i * EE * DD;
    float* wc = g_wcat + (size_t)i * EE * DD;
#pragma unroll
    for (int s = 0; s < 8; s++) wc[(DD + s) * DD + n] = wo[(DD + s) * DD + n];
    float bv = bo[(size_t)i * DD + n];
    for (int d = 0; d < DD; d++) bv += bi[(size_t)i * EE + d] * wo[(size_t)d * DD + n];
    g_bcat[(size_t)i * DD + n] = bv;
}

// ================= fp32 GEMM, 64x64x8 tiles, 8x8 microtile, 64 threads =================
// C[M,N] = A'[M,K] @ B[K,N] + bias;  A' = CONCAT ? [A(256 cols) | S(8 cols)] : A.
// cp.async double-buffered. As stored m-major with pitch 12.
// Grid: (N/64, M/64, Z). No edge guards: M,N multiples of 64; K multiple of 8.
template<bool CONCAT>
__global__ void __launch_bounds__(64)
gemm64_kernel(const float* __restrict__ A, int lda, size_t aStride,
              const float* __restrict__ S,
              const float* __restrict__ B, int ldb, size_t bStride,
              const float* __restrict__ bias,
              float* __restrict__ C, int ldc, size_t cStride,
              int K) {
    __shared__ __align__(16) float As[2][64][12];
    __shared__ __align__(16) float Bs[2][8][64];

    A += blockIdx.z * aStride;
    B += blockIdx.z * bStride;
    C += blockIdx.z * cStride;

    const int tid = threadIdx.x;
    const int tcol = tid & 7;
    const int trow = tid >> 3;
    const int row0 = blockIdx.y * 64;
    const int col0 = blockIdx.x * 64;
    const uint32_t sA = smem_u32(As);
    const uint32_t sB = smem_u32(Bs);
    const int nk = K >> 3;

    const int am = tid >> 1;             // 0..31
    const int akc = (tid & 1) * 4;       // 0 or 4
    const int br_ = tid >> 4;            // 0..3
    const int bc4 = (tid & 15) * 4;      // 0..60

    auto load_tile = [&](int kt, int buf) {
        int k0 = kt * 8;
        const float *s0, *s1;
        if (CONCAT && k0 == DD) {
            s0 = &S[(size_t)(row0 + am) * 8 + akc];
            s1 = &S[(size_t)(row0 + am + 32) * 8 + akc];
        } else {
            s0 = &A[(size_t)(row0 + am) * lda + k0 + akc];
            s1 = &A[(size_t)(row0 + am + 32) * lda + k0 + akc];
        }
        cp_async16(sA + (uint32_t)(buf * 3072 + am * 48 + akc * 4), s0);
        cp_async16(sA + (uint32_t)(buf * 3072 + (am + 32) * 48 + akc * 4), s1);
        cp_async16(sB + (uint32_t)(buf * 2048 + br_ * 256 + bc4 * 4),
                   &B[(size_t)(k0 + br_) * ldb + col0 + bc4]);
        cp_async16(sB + (uint32_t)(buf * 2048 + (br_ + 4) * 256 + bc4 * 4),
                   &B[(size_t)(k0 + br_ + 4) * ldb + col0 + bc4]);
        cp_async_commit();
    };

    float acc[8][8];
#pragma unroll
    for (int i = 0; i < 8; i++)
#pragma unroll
        for (int j = 0; j < 8; j++) acc[i][j] = 0.f;

    load_tile(0, 0);

    for (int kt = 0; kt < nk; kt++) {
        if (kt + 1 < nk) {
            load_tile(kt + 1, (kt + 1) & 1);
            cp_async_wait<1>();
        } else {
            cp_async_wait<0>();
        }
        __syncthreads();

        const float (*Ab)[12] = As[kt & 1];
        const float (*Bb)[64] = Bs[kt & 1];
#pragma unroll
        for (int k = 0; k < 8; k++) {
            float rm[8], rn[8];
#pragma unroll
            for (int i = 0; i < 8; i++) rm[i] = Ab[trow * 8 + i][k];
#pragma unroll
            for (int j = 0; j < 8; j++) rn[j] = Bb[k][tcol * 8 + j];
#pragma unroll
            for (int i = 0; i < 8; i++)
#pragma unroll
                for (int j = 0; j < 8; j++) acc[i][j] += rm[i] * rn[j];
        }
        __syncthreads();
    }

    float bv[8];
#pragma unroll
    for (int j = 0; j < 8; j++) bv[j] = bias ? bias[col0 + tcol * 8 + j] : 0.f;
#pragma unroll
    for (int i = 0; i < 8; i++) {
        int r = row0 + trow * 8 + i;
#pragma unroll
        for (int j = 0; j < 8; j += 4) {
            float4 o;
            o.x = acc[i][j + 0] + bv[j + 0];
            o.y = acc[i][j + 1] + bv[j + 1];
            o.z = acc[i][j + 2] + bv[j + 2];
            o.w = acc[i][j + 3] + bv[j + 3];
            *(float4*)(&C[(size_t)r * ldc + col0 + tcol * 8 + j]) = o;
        }
    }
}

// ---------------- skinny: g_sg[row][0..15] = h@Wsg + bsg (warp per row) ----------------
__global__ void skinny_kernel(const float* __restrict__ h, int layer) {
    int warp = threadIdx.x >> 5;
    int lane = threadIdx.x & 31;
    int row = blockIdx.x * 8 + warp;
    const float* wsg = g_wsg + (size_t)layer * DD * 16;

    float acc[16];
#pragma unroll
    for (int c = 0; c < 16; c++) acc[c] = 0.f;

    for (int e = lane; e < DD; e += 32) {
        float a = h[(size_t)row * DD + e];
        const float4* w = (const float4*)(wsg + e * 16);
        float4 w0 = w[0], w1 = w[1], w2 = w[2], w3 = w[3];
        acc[0]  += a * w0.x; acc[1]  += a * w0.y; acc[2]  += a * w0.z; acc[3]  += a * w0.w;
        acc[4]  += a * w1.x; acc[5]  += a * w1.y; acc[6]  += a * w1.z; acc[7]  += a * w1.w;
        acc[8]  += a * w2.x; acc[9]  += a * w2.y; acc[10] += a * w2.z; acc[11] += a * w2.w;
        acc[12] += a * w3.x; acc[13] += a * w3.y; acc[14] += a * w3.z; acc[15] += a * w3.w;
    }
#pragma unroll
    for (int c = 0; c < 16; c++)
#pragma unroll
        for (int off = 16; off > 0; off >>= 1)
            acc[c] += __shfl_xor_sync(0xffffffffu, acc[c], off);

    if (lane < 16) {
        float v = 0.f;
#pragma unroll
        for (int c = 0; c < 16; c++) v = (lane == c) ? acc[c] : v;
        g_sg[(size_t)row * 16 + lane] = v + g_bsg[layer * 16 + lane];
    }
}

// ---------------- scan (sigmoid inside): g_sg -> g_states, finals ----------------
__global__ void scan2_kernel(float* __restrict__ finals, int layer) {
    __shared__ float sA[256];
    __shared__ float sB[256];
    const int b = blockIdx.x >> 3;
    const int s = blockIdx.x & 7;
    const int tid = threadIdx.x;
    constexpr int CH = LL / 256;   // 8

    const int t0 = tid * CH;
    float gl[CH], cl[CH];
    float A = 1.f, Bv = 0.f;
#pragma unroll
    for (int i = 0; i < CH; i++) {
        int row = b * LL + t0 + i;
        float gp = g_sg[(size_t)row * 16 + 8 + s];
        float g = 1.f / (1.f + expf(-gp));
        float si = g_sg[(size_t)row * 16 + s];
        gl[i] = g;
        cl[i] = (1.f - g) * si;
        A  = g * A;
        Bv = g * Bv + cl[i];
    }
    sA[tid] = A; sB[tid] = Bv;
    __syncthreads();

    for (int off = 1; off < 256; off <<= 1) {
        float cA = sA[tid], cB = sB[tid];
        float pA = 1.f, pB = 0.f;
        if (tid >= off) { pA = sA[tid - off]; pB = sB[tid - off]; }
        __syncthreads();
        sA[tid] = cA * pA;
        sB[tid] = cA * pB + cB;
        __syncthreads();
    }

    float st = (tid == 0) ? 0.f : sB[tid - 1];
#pragma unroll
    for (int i = 0; i < CH; i++) {
        int row = b * LL + t0 + i;
        st = gl[i] * st + cl[i];
        g_states[(size_t)row * SS + s] = st;
    }
    if (t0 + CH == LL)
        finals[layer * BB * SS + b * SS + s] = st;
}

// ---------------- layernorm over D=256, one block per row ----------------
__global__ void ln_kernel(const float* __restrict__ gamma, const float* __restrict__ beta) {
    __shared__ float red[8];
    const int row = blockIdx.x;
    const int tid = threadIdx.x;
    const int lane = tid & 31, warp = tid >> 5;

    float x = g_h[(size_t)row * DD + tid];

    float v = x;
#pragma unroll
    for (int off = 16; off > 0; off >>= 1) v += __shfl_xor_sync(0xffffffffu, v, off);
    if (lane == 0) red[warp] = v;
    __syncthreads();
    float tot = 0.f;
#pragma unroll
    for (int i = 0; i < 8; i++) tot += red[i];
    float mu = tot * (1.f / DD);
    float d = x - mu;
    __syncthreads();

    v = d * d;
#pragma unroll
    for (int off = 16; off > 0; off >>= 1) v += __shfl_xor_sync(0xffffffffu, v, off);
    if (lane == 0) red[warp] = v;
    __syncthreads();
    float tot2 = 0.f;
#pragma unroll
    for (int i = 0; i < 8; i++) tot2 += red[i];
    float var = tot2 * (1.f / DD);

    float y = d * rsqrtf(var + 1e-5f) * gamma[tid] + beta[tid];
    g_hn[(size_t)row * DD + tid] = y;
    g_hnh[(size_t)row * DD + tid] = __float2half(y);
}

// ================= fp16 mma.sync logits GEMM (validated round 6) =================
#define GM_M 128
#define GM_N 128
#define GM_KC 64
#define GM_NCHUNK (DD / GM_KC)          // 4
#define ABUF_BYTES (GM_M * GM_KC * 2)   // 16384
#define BBUF_BYTES (GM_KC * GM_N * 2)   // 16384
#define SMEM_BYTES (2 * (ABUF_BYTES + BBUF_BYTES))  // 65536

__global__ void __launch_bounds__(256)
logits_mma_kernel(const float* __restrict__ bc, float* __restrict__ C) {
    extern __shared__ char sm[];
    const int tid = threadIdx.x;
    const int wid = tid >> 5;
    const int lane = tid & 31;
    const int warp_m = wid & 3;
    const int warp_n = wid >> 2;
    const int row0 = blockIdx.y * GM_M;
    const int col0 = blockIdx.x * GM_N;

    const uint32_t s_base = smem_u32(sm);
    const uint32_t aOff[2] = { 0u, (uint32_t)ABUF_BYTES };
    const uint32_t bOff[2] = { (uint32_t)(2 * ABUF_BYTES),
                               (uint32_t)(2 * ABUF_BYTES + BBUF_BYTES) };

    float acc[2][8][4];
#pragma unroll
    for (int mt = 0; mt < 2; mt++)
#pragma unroll
        for (int nt = 0; nt < 8; nt++)
#pragma unroll
            for (int i = 0; i < 4; i++) acc[mt][nt][i] = 0.f;

    auto load_chunk = [&](int c, int buf) {
#pragma unroll
        for (int t = 0; t < 4; t++) {
            int idx = tid + t * 256;
            int m = idx >> 3;
            int c16 = idx & 7;
            cp_async16(s_base + aOff[buf] + (uint32_t)SW128(m * 128 + c16 * 16),
                       &g_hnh[(size_t)(row0 + m) * DD + c * GM_KC + c16 * 8]);
        }
#pragma unroll
        for (int t = 0; t < 4; t++) {
            int idx = tid + t * 256;
            int k = idx >> 4;
            int c16 = idx & 15;
            int group = c16 >> 3;
            int w = (c16 & 7) ^ (k & 7);
            cp_async16(s_base + bOff[buf] + (uint32_t)(k * 256 + group * 128 + w * 16),
                       &g_wch[(size_t)(c * GM_KC + k) * VOCAB + col0 + c16 * 8]);
        }
        cp_async_commit();
    };

    load_chunk(0, 0);

    for (int c = 0; c < GM_NCHUNK; c++) {
        if (c + 1 < GM_NCHUNK) {
            load_chunk(c + 1, (c + 1) & 1);
            cp_async_wait<1>();
        } else {
            cp_async_wait<0>();
        }
        __syncthreads();

        const uint32_t sA = s_base + aOff[c & 1];
        const uint32_t sB = s_base + bOff[c & 1];

#pragma unroll
        for (int ks = 0; ks < GM_KC / 16; ks++) {
            uint32_t afr[2][4];
#pragma unroll
            for (int mt = 0; mt < 2; mt++) {
                int r = warp_m * 32 + mt * 16 + (lane & 15);
                int cb = ks * 32 + (lane >> 4) * 16;
                ldsm_x4(afr[mt], sA + (uint32_t)SW128(r * 128 + cb));
            }
            uint32_t bfr[8][2];
#pragma unroll
            for (int p = 0; p < 4; p++) {
                int k = ks * 16 + ((lane >> 3) & 1) * 8 + (lane & 7);
                int n = warp_n * 64 + p * 16 + (lane >> 4) * 8;
                int c16 = n >> 3;
                int group = c16 >> 3;
                int w = (c16 & 7) ^ (k & 7);
                uint32_t tmp[4];
                ldsm_x4_t(tmp, sB + (uint32_t)(k * 256 + group * 128 + w * 16));
                bfr[p * 2 + 0][0] = tmp[0]; bfr[p * 2 + 0][1] = tmp[1];
                bfr[p * 2 + 1][0] = tmp[2]; bfr[p * 2 + 1][1] = tmp[3];
            }
#pragma unroll
            for (int mt = 0; mt < 2; mt++)
#pragma unroll
                for (int nt = 0; nt < 8; nt++)
                    mma_f16(acc[mt][nt], afr[mt], bfr[nt]);
        }
        __syncthreads();
    }

#pragma unroll
    for (int nt = 0; nt < 8; nt++) {
        int cc = col0 + warp_n * 64 + nt * 8 + (lane & 3) * 2;
        float2 bv = *(const float2*)(&bc[cc]);
#pragma unroll
        for (int mt = 0; mt < 2; mt++) {
            int r = row0 + warp_m * 32 + mt * 16 + (lane >> 2);
            float2 v0 = make_float2(acc[mt][nt][0] + bv.x, acc[mt][nt][1] + bv.y);
            float2 v1 = make_float2(acc[mt][nt][2] + bv.x, acc[mt][nt][3] + bv.y);
            *(float2*)(&C[(size_t)r * VOCAB + cc]) = v0;
            *(float2*)(&C[(size_t)(r + 8) * VOCAB + cc]) = v1;
        }
    }
}

// ---------------- launch ----------------
extern "C" void kernel_launch(void* const* d_in, const int* in_sizes, int n_in,
                              void* d_out, int out_size) {
    const int*   x_t   = (const int*)  d_in[0];
    const float* table = (const float*)d_in[1];
    const float* Wi    = (const float*)d_in[2];
    const float* bi    = (const float*)d_in[3];
    const float* Wg    = (const float*)d_in[4];
    const float* bg    = (const float*)d_in[5];
    const float* Wo    = (const float*)d_in[6];
    const float* bo    = (const float*)d_in[7];
    const float* gamma = (const float*)d_in[8];
    const float* beta  = (const float*)d_in[9];
    const float* Wc    = (const float*)d_in[10];
    const float* bc    = (const float*)d_in[11];
    const float* Wr    = (const float*)d_in[12];
    const float* br    = (const float*)d_in[13];

    float* out    = (float*)d_out;
    float* logits = out;
    float* recon  = out + (size_t)ROWS * VOCAB;
    float* finals = recon + (size_t)ROWS * DD;

    float *h_p = nullptr, *h2_p = nullptr, *hn_p = nullptr;
    float *states_p = nullptr, *wcat_p = nullptr, *bcat_p = nullptr;
    cudaGetSymbolAddress((void**)&h_p,      g_h);
    cudaGetSymbolAddress((void**)&h2_p,     g_h2);
    cudaGetSymbolAddress((void**)&hn_p,     g_hn);
    cudaGetSymbolAddress((void**)&states_p, g_states);
    cudaGetSymbolAddress((void**)&wcat_p,   g_wcat);
    cudaGetSymbolAddress((void**)&bcat_p,   g_bcat);

    cudaFuncSetAttribute(logits_mma_kernel,
                         cudaFuncAttributeMaxDynamicSharedMemorySize, SMEM_BYTES);

    // ---- inputs / precompute ----
    embed_kernel<<<ROWS, DD>>>(x_t, table);
    convert_wc_kernel<<<(DD * VOCAB) / 1024, 256>>>(Wc);
    wf_kernel<<<DEPTH, DD>>>(Wi, bi, Wg, bg);
    // Wcat rows 0..255 = Wi1 @ Wo1 for all 4 layers (z-batched)
    gemm64_kernel<false><<<dim3(DD / 64, DD / 64, DEPTH), 64>>>(
        Wi, EE, (size_t)DD * EE, nullptr,
        Wo, DD, (size_t)EE * DD,
        nullptr,
        wcat_p, DD, (size_t)EE * DD, DD);
    wcat_tail_kernel<<<DEPTH, DD>>>(Wo, bi, bo);

    // ---- layers ----
    for (int i = 0; i < DEPTH; i++) {
        const float* hin = (i & 1) ? h2_p : h_p;
        float*       hout = (i & 1) ? h_p  : h2_p;
        skinny_kernel<<<ROWS / 8, 256>>>(hin, i);
        scan2_kernel<<<BB * SS, 256>>>(finals, i);
        gemm64_kernel<true><<<dim3(DD / 64, ROWS / 64), 64>>>(
            hin, DD, 0, states_p,
            wcat_p + (size_t)i * EE * DD, DD, 0,
            bcat_p + (size_t)i * DD,
            hout, DD, 0, EE);
    }

    ln_kernel<<<ROWS, DD>>>(gamma, beta);

    // logits via fp16 mma.sync
    logits_mma_kernel<<<dim3(VOCAB / GM_N, ROWS / GM_M), 256, SMEM_BYTES>>>(bc, logits);

    // recon = hn @ Wr + br (fp32)
    gemm64_kernel<false><<<dim3(DD / 64, ROWS / 64), 64>>>(
        hn_p, DD, 0, nullptr, Wr, DD, 0, br, recon, DD, 0, DD);
}